// round 9
// baseline (speedup 1.0000x reference)
#include <cuda_runtime.h>

#define NPTS 1000000
#define TR_ELEMS 5898240   // 3072 * (128+256+512+1024)

// Transposed grids: layout [scale][ci][y][x][f], f contiguous (16 floats = 64B per corner)
__device__ float g_tr[TR_ELEMS];

// ---------------------------------------------------------------------------
// Transpose [3, 16, H, 64] (f-major) -> [3, H, 64, 16] (f-minor)
// One block per (ci, y) row. Coalesced reads and writes via smem tile.
// ---------------------------------------------------------------------------
__global__ void transpose_kernel(const float* __restrict__ g, int H, int off) {
    __shared__ float s[16][65];
    int ci = blockIdx.x / H;
    int y  = blockIdx.x - ci * H;

    const float* gp = g + (size_t)ci * 16 * H * 64;
    for (int i = threadIdx.x; i < 1024; i += blockDim.x) {
        int f = i >> 6, x = i & 63;
        s[f][x] = gp[((size_t)f * H + y) * 64 + x];
    }
    __syncthreads();
    float* tp = g_tr + off + (size_t)(ci * H + y) * 64 * 16;
    for (int i = threadIdx.x; i < 1024; i += blockDim.x) {
        int x = i >> 4, f = i & 15;
        tp[x * 16 + f] = s[f][x];
    }
}

// ---------------------------------------------------------------------------
// Sample kernel: 4 threads per point, lane l handles features [4l, 4l+4)
// Per (scale, plane): 4x LDG.128 (corners) + weighted combine + 1x STG.128
// ---------------------------------------------------------------------------
__global__ void __launch_bounds__(256) sample_kernel(const float* __restrict__ pts,
                                                     const float* __restrict__ rad,
                                                     float* __restrict__ out) {
    int gid = blockIdx.x * blockDim.x + threadIdx.x;
    int pt = gid >> 2;
    int l  = gid & 3;
    if (pt >= NPTS) return;

    float pc[3];
    pc[0] = pts[pt * 3 + 0];
    pc[1] = pts[pt * 3 + 1];
    pc[2] = pts[pt * 3 + 2];
    float r = rad[pt];

    // x-dimension (W=64) is identical across all 4 scales: precompute per plane
    int x0[3], x1[3];
    float wx[3];
#pragma unroll
    for (int ci = 0; ci < 3; ci++) {
        float tx = (pc[ci] + 1.0f) * 0.5f * 63.0f;
        float xf = floorf(tx);
        wx[ci] = tx - xf;
        int xi = (int)xf;
        x0[ci] = min(max(xi, 0), 63);
        x1[ci] = min(max(xi + 1, 0), 63);
    }

    float* op = out + (size_t)pt * 192 + l * 4;

    const int Hs[4]  = {128, 256, 512, 1024};
    const int OFF[4] = {0, 393216, 1179648, 2752512};

#pragma unroll
    for (int si = 0; si < 4; si++) {
        const int H = Hs[si];
        float ty = (r + 1.0f) * 0.5f * (float)(H - 1);
        float yf = floorf(ty);
        float wy = ty - yf;
        int yi = (int)yf;
        int y0 = min(max(yi, 0), H - 1);
        int y1 = min(max(yi + 1, 0), H - 1);

        const float* base = g_tr + OFF[si];
#pragma unroll
        for (int ci = 0; ci < 3; ci++) {
            int row0 = (ci * H + y0) * 64;
            int row1 = (ci * H + y1) * 64;
            const float4* p00 = (const float4*)(base + (size_t)(row0 + x0[ci]) * 16) + l;
            const float4* p01 = (const float4*)(base + (size_t)(row0 + x1[ci]) * 16) + l;
            const float4* p10 = (const float4*)(base + (size_t)(row1 + x0[ci]) * 16) + l;
            const float4* p11 = (const float4*)(base + (size_t)(row1 + x1[ci]) * 16) + l;

            float4 g00 = __ldg(p00);
            float4 g01 = __ldg(p01);
            float4 g10 = __ldg(p10);
            float4 g11 = __ldg(p11);

            float w00 = (1.0f - wy) * (1.0f - wx[ci]);
            float w01 = (1.0f - wy) * wx[ci];
            float w10 = wy * (1.0f - wx[ci]);
            float w11 = wy * wx[ci];

            float4 v;
            v.x = g00.x * w00 + g01.x * w01 + g10.x * w10 + g11.x * w11;
            v.y = g00.y * w00 + g01.y * w01 + g10.y * w10 + g11.y * w11;
            v.z = g00.z * w00 + g01.z * w01 + g10.z * w10 + g11.z * w11;
            v.w = g00.w * w00 + g01.w * w01 + g10.w * w10 + g11.w * w11;

            *(float4*)(op + si * 48 + ci * 16) = v;
        }
    }
}

extern "C" void kernel_launch(void* const* d_in, const int* in_sizes, int n_in,
                              void* d_out, int out_size) {
    const float* pts = (const float*)d_in[0];
    const float* rad = (const float*)d_in[1];
    const float* g0  = (const float*)d_in[2];
    const float* g1  = (const float*)d_in[3];
    const float* g2  = (const float*)d_in[4];
    const float* g3  = (const float*)d_in[5];
    float* out = (float*)d_out;

    // Transposes: one block per (ci, y) row
    transpose_kernel<<<3 * 128, 256>>>(g0, 128, 0);
    transpose_kernel<<<3 * 256, 256>>>(g1, 256, 393216);
    transpose_kernel<<<3 * 512, 256>>>(g2, 512, 1179648);
    transpose_kernel<<<3 * 1024, 256>>>(g3, 1024, 2752512);

    // Sampling: 4 threads per point
    int threads = 4 * NPTS;
    sample_kernel<<<(threads + 255) / 256, 256>>>(pts, rad, out);
}

// round 14
// speedup vs baseline: 1.0764x; 1.0764x over previous
#include <cuda_runtime.h>
#include <cuda_fp16.h>

#define NPTS 1000000
#define TR_ELEMS 5898240   // 3072 * (128+256+512+1024)

// Transposed grids in fp16: layout [scale][ci][y][x][f], f contiguous (16 halfs = 32B per corner)
__device__ __half g_tr_h[TR_ELEMS];

// ---------------------------------------------------------------------------
// Fused transpose+convert: [3,16,H,64] fp32 (f-major) -> [3,H,64,16] fp16 (f-minor)
// One block per (ci, y) row across all 4 scales.
// Block ranges: g0:[0,384) g1:[384,1152) g2:[1152,2688) g3:[2688,5760)
// ---------------------------------------------------------------------------
__global__ void transpose_all_kernel(const float* __restrict__ g0,
                                     const float* __restrict__ g1,
                                     const float* __restrict__ g2,
                                     const float* __restrict__ g3) {
    __shared__ float s[16][65];
    int b = blockIdx.x;
    const float* g; int H, off, rel;
    if (b < 384)       { g = g0; H = 128;  off = 0;       rel = b; }
    else if (b < 1152) { g = g1; H = 256;  off = 393216;  rel = b - 384; }
    else if (b < 2688) { g = g2; H = 512;  off = 1179648; rel = b - 1152; }
    else               { g = g3; H = 1024; off = 2752512; rel = b - 2688; }
    int ci = rel / H;
    int y  = rel - ci * H;

    const float* gp = g + (size_t)ci * 16 * H * 64;
    for (int i = threadIdx.x; i < 1024; i += blockDim.x) {
        int f = i >> 6, x = i & 63;
        s[f][x] = gp[((size_t)f * H + y) * 64 + x];
    }
    __syncthreads();
    __half* tp = g_tr_h + off + (size_t)(ci * H + y) * 64 * 16;
    for (int i = threadIdx.x; i < 1024; i += blockDim.x) {
        int x = i >> 4, f = i & 15;
        tp[x * 16 + f] = __float2half(s[f][x]);
    }
}

// Load 4 consecutive fp16 values as float4 (one 8B LDG.64)
__device__ __forceinline__ float4 ld4h(const __half* p) {
    uint2 r = *reinterpret_cast<const uint2*>(p);
    __half2 h0 = *reinterpret_cast<const __half2*>(&r.x);
    __half2 h1 = *reinterpret_cast<const __half2*>(&r.y);
    float2 f0 = __half22float2(h0);
    float2 f1 = __half22float2(h1);
    return make_float4(f0.x, f0.y, f1.x, f1.y);
}

// ---------------------------------------------------------------------------
// Sample kernel: 4 threads per point, lane l handles features [4l, 4l+4)
// Per (scale, plane): 4x LDG.64 (fp16 corners) + fp32 combine + 1x STG.128
// ---------------------------------------------------------------------------
__global__ void __launch_bounds__(256) sample_kernel(const float* __restrict__ pts,
                                                     const float* __restrict__ rad,
                                                     float* __restrict__ out) {
    int gid = blockIdx.x * blockDim.x + threadIdx.x;
    int pt = gid >> 2;
    int l  = gid & 3;
    if (pt >= NPTS) return;

    float pc[3];
    pc[0] = pts[pt * 3 + 0];
    pc[1] = pts[pt * 3 + 1];
    pc[2] = pts[pt * 3 + 2];
    float r = rad[pt];

    // x-dimension (W=64) is identical across all 4 scales: precompute per plane
    int x0[3], x1[3];
    float wx[3];
#pragma unroll
    for (int ci = 0; ci < 3; ci++) {
        float tx = (pc[ci] + 1.0f) * 0.5f * 63.0f;
        float xf = floorf(tx);
        wx[ci] = tx - xf;
        int xi = (int)xf;
        x0[ci] = min(max(xi, 0), 63);
        x1[ci] = min(max(xi + 1, 0), 63);
    }

    float* op = out + (size_t)pt * 192 + l * 4;

    const int Hs[4]  = {128, 256, 512, 1024};
    const int OFF[4] = {0, 393216, 1179648, 2752512};

#pragma unroll
    for (int si = 0; si < 4; si++) {
        const int H = Hs[si];
        float ty = (r + 1.0f) * 0.5f * (float)(H - 1);
        float yf = floorf(ty);
        float wy = ty - yf;
        int yi = (int)yf;
        int y0 = min(max(yi, 0), H - 1);
        int y1 = min(max(yi + 1, 0), H - 1);

        const __half* base = g_tr_h + OFF[si];
#pragma unroll
        for (int ci = 0; ci < 3; ci++) {
            int row0 = (ci * H + y0) * 64;
            int row1 = (ci * H + y1) * 64;
            int lo = l * 4;

            float4 g00 = ld4h(base + (size_t)(row0 + x0[ci]) * 16 + lo);
            float4 g01 = ld4h(base + (size_t)(row0 + x1[ci]) * 16 + lo);
            float4 g10 = ld4h(base + (size_t)(row1 + x0[ci]) * 16 + lo);
            float4 g11 = ld4h(base + (size_t)(row1 + x1[ci]) * 16 + lo);

            float w00 = (1.0f - wy) * (1.0f - wx[ci]);
            float w01 = (1.0f - wy) * wx[ci];
            float w10 = wy * (1.0f - wx[ci]);
            float w11 = wy * wx[ci];

            float4 v;
            v.x = g00.x * w00 + g01.x * w01 + g10.x * w10 + g11.x * w11;
            v.y = g00.y * w00 + g01.y * w01 + g10.y * w10 + g11.y * w11;
            v.z = g00.z * w00 + g01.z * w01 + g10.z * w10 + g11.z * w11;
            v.w = g00.w * w00 + g01.w * w01 + g10.w * w10 + g11.w * w11;

            *(float4*)(op + si * 48 + ci * 16) = v;
        }
    }
}

extern "C" void kernel_launch(void* const* d_in, const int* in_sizes, int n_in,
                              void* d_out, int out_size) {
    const float* pts = (const float*)d_in[0];
    const float* rad = (const float*)d_in[1];
    const float* g0  = (const float*)d_in[2];
    const float* g1  = (const float*)d_in[3];
    const float* g2  = (const float*)d_in[4];
    const float* g3  = (const float*)d_in[5];
    float* out = (float*)d_out;

    // Fused transpose+convert: 5760 blocks = 3*(128+256+512+1024)
    transpose_all_kernel<<<5760, 256>>>(g0, g1, g2, g3);

    // Sampling: 4 threads per point
    int threads = 4 * NPTS;
    sample_kernel<<<(threads + 255) / 256, 256>>>(pts, rad, out);
}

// round 17
// speedup vs baseline: 1.4562x; 1.3528x over previous
#include <cuda_runtime.h>
#include <cuda_fp16.h>

#define NPTS 1000000
// Pair layout: [scale][ci][y][x][f][2] halfs; entry(ci,y,x) = 64B = 16 x half2(g[x][f], g[x+1][f])
#define PAIR_ELEMS 11796480   // 2 * 3072 * (128+256+512+1024)

__device__ __half2 g_pair[PAIR_ELEMS / 2];

// ---------------------------------------------------------------------------
// Fused transpose+convert+pair: [3,16,H,64] fp32 -> [3,H,64,16] half2 x-pairs
// One block per (ci, y) row across all 4 scales.
// Block ranges: g0:[0,384) g1:[384,1152) g2:[1152,2688) g3:[2688,5760)
// Scale offsets in half2 units: {0, 393216, 1179648, 2752512}
// ---------------------------------------------------------------------------
__global__ void transpose_all_kernel(const float* __restrict__ g0,
                                     const float* __restrict__ g1,
                                     const float* __restrict__ g2,
                                     const float* __restrict__ g3) {
    __shared__ float s[16][65];
    int b = blockIdx.x;
    const float* g; int H, off, rel;
    if (b < 384)       { g = g0; H = 128;  off = 0;       rel = b; }
    else if (b < 1152) { g = g1; H = 256;  off = 393216;  rel = b - 384; }
    else if (b < 2688) { g = g2; H = 512;  off = 1179648; rel = b - 1152; }
    else               { g = g3; H = 1024; off = 2752512; rel = b - 2688; }
    int ci = rel / H;
    int y  = rel - ci * H;

    const float* gp = g + (size_t)ci * 16 * H * 64;
    for (int i = threadIdx.x; i < 1024; i += blockDim.x) {
        int f = i >> 6, x = i & 63;
        s[f][x] = gp[((size_t)f * H + y) * 64 + x];
    }
    __syncthreads();
    // Row of 64 entries, each 16 half2: half2 index within row = x*16 + f
    __half2* tp = g_pair + off + (size_t)(ci * H + y) * 1024;
    for (int i = threadIdx.x; i < 1024; i += blockDim.x) {
        int x = i >> 4, f = i & 15;
        int xn = min(x + 1, 63);
        tp[i] = __floats2half2_rn(s[f][x], s[f][xn]);
    }
}

// ---------------------------------------------------------------------------
// Sample kernel: 4 threads per point, lane l handles features [4l, 4l+4)
// Per (scale, plane): 2x LDG.128 (x-paired rows y0, y1) + fp32 lerp + STG.128
// ---------------------------------------------------------------------------
__global__ void __launch_bounds__(256) sample_kernel(const float* __restrict__ pts,
                                                     const float* __restrict__ rad,
                                                     float* __restrict__ out) {
    int gid = blockIdx.x * blockDim.x + threadIdx.x;
    int pt = gid >> 2;
    int l  = gid & 3;
    if (pt >= NPTS) return;

    float pc[3];
    pc[0] = pts[pt * 3 + 0];
    pc[1] = pts[pt * 3 + 1];
    pc[2] = pts[pt * 3 + 2];
    float r = rad[pt];

    int x0[3];
    float wx[3];
#pragma unroll
    for (int ci = 0; ci < 3; ci++) {
        float tx = (pc[ci] + 1.0f) * 0.5f * 63.0f;
        float xf = floorf(tx);
        wx[ci] = tx - xf;
        x0[ci] = min(max((int)xf, 0), 63);
    }

    float* op = out + (size_t)pt * 192 + l * 4;

    const int Hs[4]   = {128, 256, 512, 1024};
    const int OFFP[4] = {0, 393216, 1179648, 2752512};  // half2 units

#pragma unroll
    for (int si = 0; si < 4; si++) {
        const int H = Hs[si];
        float ty = (r + 1.0f) * 0.5f * (float)(H - 1);
        float yf = floorf(ty);
        float wy = ty - yf;
        int yi = (int)yf;
        int y0 = min(max(yi, 0), H - 1);
        int y1 = min(max(yi + 1, 0), H - 1);

        const __half2* base = g_pair + OFFP[si];
#pragma unroll
        for (int ci = 0; ci < 3; ci++) {
            // entry index (in half2): ((ci*H + y)*64 + x) * 16 ; lane covers f[4l..4l+4) -> +4l
            const uint4* p0 = (const uint4*)(base + ((size_t)(ci * H + y0) * 64 + x0[ci]) * 16 + l * 4);
            const uint4* p1 = (const uint4*)(base + ((size_t)(ci * H + y1) * 64 + x0[ci]) * 16 + l * 4);

            uint4 r0 = __ldg(p0);
            uint4 r1 = __ldg(p1);

            float w = wx[ci];
            float wyc = 1.0f - wy;

            float2 a0 = __half22float2(*(const __half2*)&r0.x);
            float2 a1 = __half22float2(*(const __half2*)&r0.y);
            float2 a2 = __half22float2(*(const __half2*)&r0.z);
            float2 a3 = __half22float2(*(const __half2*)&r0.w);
            float2 b0 = __half22float2(*(const __half2*)&r1.x);
            float2 b1 = __half22float2(*(const __half2*)&r1.y);
            float2 b2 = __half22float2(*(const __half2*)&r1.z);
            float2 b3 = __half22float2(*(const __half2*)&r1.w);

            float4 v;
            v.x = (a0.x * (1.0f - w) + a0.y * w) * wyc + (b0.x * (1.0f - w) + b0.y * w) * wy;
            v.y = (a1.x * (1.0f - w) + a1.y * w) * wyc + (b1.x * (1.0f - w) + b1.y * w) * wy;
            v.z = (a2.x * (1.0f - w) + a2.y * w) * wyc + (b2.x * (1.0f - w) + b2.y * w) * wy;
            v.w = (a3.x * (1.0f - w) + a3.y * w) * wyc + (b3.x * (1.0f - w) + b3.y * w) * wy;

            *(float4*)(op + si * 48 + ci * 16) = v;
        }
    }
}

extern "C" void kernel_launch(void* const* d_in, const int* in_sizes, int n_in,
                              void* d_out, int out_size) {
    const float* pts = (const float*)d_in[0];
    const float* rad = (const float*)d_in[1];
    const float* g0  = (const float*)d_in[2];
    const float* g1  = (const float*)d_in[3];
    const float* g2  = (const float*)d_in[4];
    const float* g3  = (const float*)d_in[5];
    float* out = (float*)d_out;

    transpose_all_kernel<<<5760, 256>>>(g0, g1, g2, g3);

    int threads = 4 * NPTS;
    sample_kernel<<<(threads + 255) / 256, 256>>>(pts, rad, out);
}